// round 14
// baseline (speedup 1.0000x reference)
#include <cuda_runtime.h>
#include <cuda_bf16.h>
#include <cstdint>
#include <cfloat>

// ---------------------------------------------------------------------------
// Problem constants
// ---------------------------------------------------------------------------
#define M_TOTAL 16384
#define K_CODES 8192
#define DIM     512
#define MT      64              // rows per CTA (2 CTAs/SM)
#define BN      256             // codes per chunk; warp tile 64x32
#define NCHUNK  (K_CODES / BN)  // 32
#define BK      32              // bf16 K per pipeline step (64 B/row)
#define KSTEPS  (DIM / BK)      // 16
#define NSTEPS  (NCHUNK * KSTEPS) // 512
#define NTHR    256
#define IDXMASK 0x1FFFu         // 13 bits: code index embedded in mantissa

// ---------------------------------------------------------------------------
// Scratch (static device arrays: allocation-free rule)
// ---------------------------------------------------------------------------
__device__ __nv_bfloat16 g_Bb[(size_t)K_CODES * DIM];   // bf16(emb)  8 MB
__device__ float g_e2[K_CODES];
__device__ int   g_top8[M_TOTAL][8];

// ---------------------------------------------------------------------------
// Baseline-PTX helpers (no "a"-suffix arch features)
// ---------------------------------------------------------------------------
__device__ __forceinline__ uint32_t smem_u32(const void* p) {
    uint32_t a;
    asm("{ .reg .u64 t; cvta.to.shared.u64 t, %1; cvt.u32.u64 %0, t; }"
        : "=r"(a) : "l"(p));
    return a;
}

__device__ __forceinline__ void cp_async16g(uint32_t dst, uint64_t gsrc) {
    asm volatile("cp.async.cg.shared.global [%0], [%1], 16;"
                 :: "r"(dst), "l"(gsrc) : "memory");
}
#define CP_COMMIT() asm volatile("cp.async.commit_group;" ::: "memory")

__device__ __forceinline__ void ldmatrix_x4(uint32_t& r0, uint32_t& r1,
                                            uint32_t& r2, uint32_t& r3,
                                            uint32_t addr) {
    asm volatile("ldmatrix.sync.aligned.m8n8.x4.shared.b16 {%0,%1,%2,%3}, [%4];"
                 : "=r"(r0), "=r"(r1), "=r"(r2), "=r"(r3) : "r"(addr));
}

__device__ __forceinline__ void mma_bf16(float& d0, float& d1, float& d2, float& d3,
                                         uint32_t a0, uint32_t a1, uint32_t a2, uint32_t a3,
                                         uint32_t b0, uint32_t b1) {
    asm volatile(
        "mma.sync.aligned.m16n8k16.row.col.f32.bf16.bf16.f32 "
        "{%0,%1,%2,%3}, {%4,%5,%6,%7}, {%8,%9}, {%0,%1,%2,%3};"
        : "+f"(d0), "+f"(d1), "+f"(d2), "+f"(d3)
        : "r"(a0), "r"(a1), "r"(a2), "r"(a3), "r"(b0), "r"(b1));
}

// Embed code index in low 13 mantissa bits (single LOP3).
__device__ __forceinline__ float embed_idx(float s, uint32_t idx) {
    uint32_t r;
    asm("lop3.b32 %0, %1, %2, %3, 0xEA;"     // (a & b) | c
        : "=r"(r) : "r"(__float_as_uint(s)), "r"(~IDXMASK), "r"(idx));
    return __uint_as_float(r);
}

// Branchless top-2 (values carry their index).
__device__ __forceinline__ void top2f(float& b1, float& b2, float s) {
    float hi = fmaxf(b1, s);
    float lo = fminf(b1, s);
    b1 = hi;
    b2 = fmaxf(b2, lo);
}

// ---------------------------------------------------------------------------
// SMEM layout: A persistent 64 KB + B 3 stages x 16 KB -> 112 KB, 2 CTAs/SM.
// Each B stage = 8 warp-private slices of 2 KB (32 rows x 64 B).
// ---------------------------------------------------------------------------
#define SM_A       0                          // 64 rows x 1024 B
#define SM_B       65536
#define B_STAGE    16384
#define W_SLICE    2048
#define SMEM_TOTAL (SM_B + 3 * B_STAGE)       // 114688

// ---------------------------------------------------------------------------
// Fused kernel: g_Bb = bf16(emb), g_e2[k] = ||emb_k||^2 (one emb read pass)
// ---------------------------------------------------------------------------
__global__ void cvt_e2_kernel(const float* __restrict__ emb) {
    int row  = blockIdx.x * 8 + (threadIdx.x >> 5);
    int lane = threadIdx.x & 31;
    const float4* p = reinterpret_cast<const float4*>(emb + (size_t)row * DIM);
    __nv_bfloat162* o = reinterpret_cast<__nv_bfloat162*>(g_Bb) + (size_t)row * 256;
    float s = 0.f;
#pragma unroll
    for (int i = 0; i < 4; ++i) {
        int idx = lane + i * 32;
        float4 v = p[idx];
        s += v.x * v.x + v.y * v.y + v.z * v.z + v.w * v.w;
        o[idx * 2 + 0] = __floats2bfloat162_rn(v.x, v.y);
        o[idx * 2 + 1] = __floats2bfloat162_rn(v.z, v.w);
    }
#pragma unroll
    for (int off = 16; off; off >>= 1) s += __shfl_xor_sync(0xffffffffu, s, off);
    if (lane == 0) g_e2[row] = s;
}

// ---------------------------------------------------------------------------
// Top-8 insert on embedded-score floats (descending)
// ---------------------------------------------------------------------------
__device__ __forceinline__ void top8_ins(float* b, float s) {
    if (s <= b[7]) return;
    int p = 7;
#pragma unroll
    for (int t = 0; t < 7; ++t) {
        if (p > 0 && s > b[p - 1]) { b[p] = b[p - 1]; --p; }
    }
    b[p] = s;
}

// ---------------------------------------------------------------------------
// Main kernel: bf16 HMMA, warp tile 64x32, fully warp-private B pipelines.
// A is converted fp32->bf16 in the prologue (no separate cvt_x pass).
// No bar.sync anywhere in the k-loop.
// ---------------------------------------------------------------------------
__global__ void __launch_bounds__(NTHR, 2)
vq_main_kernel(const float* __restrict__ x) {
    extern __shared__ char smem[];
    uint32_t sb = smem_u32(smem);

    const int tid  = threadIdx.x;
    const int lane = tid & 31;
    const int w    = tid >> 5;     // warp 0..7: owns codes [w*32, w*32+32) per chunk
    const int q    = lane & 3;
    const int m0   = blockIdx.x * MT;

    // Per-thread B-fill constants. Thread covers rows row0+8j (j=0..3), chunk c0.
    const int row0 = lane >> 2;               // 0..7
    const int c0   = lane & 3;
    uint64_t gB;
    asm("cvta.to.global.u64 %0, %1;" : "=l"(gB) : "l"(g_Bb));
    const uint64_t pbase = gB
        + (uint32_t)(((w * 32 + row0) * 512 + c0 * 8) * 2);           // bytes
    const uint32_t d0 = (uint32_t)(w * W_SLICE + row0 * 64
                                   + ((c0 ^ ((row0 >> 1) & 3)) * 16));

    // ---- Issue B fills for gs=0 (G0) and gs=1 (G1) FIRST (async) ----
    {
        uint32_t fb = sb + SM_B + 0 * B_STAGE + d0;
#pragma unroll
        for (int j = 0; j < 4; ++j) cp_async16g(fb + j * 512, pbase + j * 8192);
        CP_COMMIT();
    }
    {
        uint32_t fb = sb + SM_B + 1 * B_STAGE + d0;
#pragma unroll
        for (int j = 0; j < 4; ++j) cp_async16g(fb + j * 512, pbase + 64 + j * 8192);
        CP_COMMIT();
    }

    // ---- Prologue: load x fp32, convert to bf16, store into swizzled A ----
    // Runs while the B fills are in flight. 4096 16B bf16 chunks; each chunk
    // = 8 bf16 = 2 float4 loads from x.
#pragma unroll
    for (int j = 0; j < 16; ++j) {
        int id = tid + j * 256;
        int row = id >> 6, c = id & 63;       // 64 chunks per 1024B A row
        const float4* src = reinterpret_cast<const float4*>(
            x + (size_t)(m0 + row) * DIM + c * 8);
        float4 v0 = src[0];
        float4 v1 = src[1];
        uint4 pk;
        pk.x = __float_as_uint(0.f); // placeholder init (overwritten below)
        __nv_bfloat162 b0 = __floats2bfloat162_rn(v0.x, v0.y);
        __nv_bfloat162 b1 = __floats2bfloat162_rn(v0.z, v0.w);
        __nv_bfloat162 b2 = __floats2bfloat162_rn(v1.x, v1.y);
        __nv_bfloat162 b3 = __floats2bfloat162_rn(v1.z, v1.w);
        pk.x = *reinterpret_cast<uint32_t*>(&b0);
        pk.y = *reinterpret_cast<uint32_t*>(&b1);
        pk.z = *reinterpret_cast<uint32_t*>(&b2);
        pk.w = *reinterpret_cast<uint32_t*>(&b3);
        uint32_t dst = sb + SM_A + row * 1024 + (c >> 3) * 128
                       + (((c & 7) ^ (row & 7)) * 16);
        *reinterpret_cast<uint4*>(smem + (dst - sb)) = pk;
    }

    asm volatile("cp.async.wait_group 1;" ::: "memory");   // G0: slice0 done
    __syncthreads();                           // A (STS) + step0 visible

    // per-thread running top-2 (embedded-index floats) for 8 row-slots [mf][h]
    float tb1[4][2], tb2[4][2];
#pragma unroll
    for (int a = 0; a < 4; ++a)
#pragma unroll
        for (int b = 0; b < 2; ++b) { tb1[a][b] = -FLT_MAX; tb2[a][b] = -FLT_MAX; }

    int sr = 0;                                // gs % 3
#pragma unroll 1
    for (int ch = 0; ch < NCHUNK; ++ch) {
        const int n0 = ch * BN;

        float acc[4][4][4];
#pragma unroll
        for (int a = 0; a < 4; ++a)
#pragma unroll
            for (int b = 0; b < 4; ++b)
#pragma unroll
                for (int c = 0; c < 4; ++c) acc[a][b][c] = 0.f;

#pragma unroll 1
        for (int st = 0; st < KSTEPS; ++st) {
            const int gs = ch * KSTEPS + st;

            // ---- A fragments for sub 0 (persistent smem; no dependency) ----
            uint32_t afr[4][4];
#pragma unroll
            for (int mf = 0; mf < 4; ++mf) {
                int row = mf * 16 + (lane & 15);
                int cA  = (st * 2) * 2 + (lane >> 4);   // k16 = st*2
                uint32_t addr = sb + SM_A + row * 1024 + (cA >> 3) * 128
                                + (((cA & 7) ^ (row & 7)) * 16);
                ldmatrix_x4(afr[mf][0], afr[mf][1], afr[mf][2], afr[mf][3], addr);
            }

            // Refill stage (gs+2)%3 BEFORE the wait (read-complete at gs-1).
            const int sf = (sr >= 1) ? (sr - 1) : 2;
            if (gs + 2 < NSTEPS) {
                const int g2 = gs + 2;
                uint64_t src = pbase
                    + (uint32_t)(((g2 >> 4) << 18) + ((g2 & 15) << 6));
                uint32_t fb = sb + SM_B + sf * B_STAGE + d0;
#pragma unroll
                for (int j = 0; j < 4; ++j)
                    cp_async16g(fb + j * 512, src + j * 8192);
                CP_COMMIT();
            } else {
                CP_COMMIT();           // keep group arithmetic uniform
            }

            // Own fill of stage gs%3 complete (newest group stays in flight).
            asm volatile("cp.async.wait_group 1;" ::: "memory");

            const uint32_t bb = sb + SM_B + sr * B_STAGE + w * W_SLICE;

#pragma unroll
            for (int sub = 0; sub < 2; ++sub) {        // 2 x k16 per BK=32
                if (sub == 1) {
#pragma unroll
                    for (int mf = 0; mf < 4; ++mf) {
                        int row = mf * 16 + (lane & 15);
                        int cA  = (st * 2 + 1) * 2 + (lane >> 4);
                        uint32_t addr = sb + SM_A + row * 1024 + (cA >> 3) * 128
                                        + (((cA & 7) ^ (row & 7)) * 16);
                        ldmatrix_x4(afr[mf][0], afr[mf][1],
                                    afr[mf][2], afr[mf][3], addr);
                    }
                }
                // ---- B fragments: 4 n-frags (8 codes each) = 2 ldmatrix.x4 ----
                uint32_t bfr[4][2];
#pragma unroll
                for (int p = 0; p < 2; ++p) {
                    int mi   = lane >> 3;
                    int noff = (mi >> 1) * 8;
                    int kc   = mi & 1;
                    int rloc = p * 16 + noff + (lane & 7);   // 0..31
                    int c    = sub * 2 + kc;
                    uint32_t addr = bb + rloc * 64
                                    + ((c ^ ((rloc >> 1) & 3)) * 16);
                    ldmatrix_x4(bfr[p*2][0], bfr[p*2][1],
                                bfr[p*2+1][0], bfr[p*2+1][1], addr);
                }
#pragma unroll
                for (int mf = 0; mf < 4; ++mf)
#pragma unroll
                    for (int nf = 0; nf < 4; ++nf)
                        mma_bf16(acc[mf][nf][0], acc[mf][nf][1],
                                 acc[mf][nf][2], acc[mf][nf][3],
                                 afr[mf][0], afr[mf][1], afr[mf][2], afr[mf][3],
                                 bfr[nf][0], bfr[nf][1]);
            }
            sr = (sr == 2) ? 0 : sr + 1;
        }

        // ---- epilogue: branchless embedded-index top-2 (no barriers) ----
        float e2h[8];
#pragma unroll
        for (int nf = 0; nf < 4; ++nf) {
            float2 p = *reinterpret_cast<const float2*>(
                &g_e2[n0 + w * 32 + nf * 8 + q * 2]);
            e2h[nf * 2] = 0.5f * p.x; e2h[nf * 2 + 1] = 0.5f * p.y;
        }
#pragma unroll
        for (int mf = 0; mf < 4; ++mf)
#pragma unroll
            for (int h = 0; h < 2; ++h)
#pragma unroll
                for (int nf = 0; nf < 4; ++nf) {
                    uint32_t cloc = (uint32_t)(n0 + w * 32 + nf * 8 + q * 2);
                    float s0 = embed_idx(acc[mf][nf][h*2+0] - e2h[nf*2+0], cloc);
                    float s1 = embed_idx(acc[mf][nf][h*2+1] - e2h[nf*2+1], cloc + 1);
                    top2f(tb1[mf][h], tb2[mf][h], s0);
                    top2f(tb1[mf][h], tb2[mf][h], s1);
                }
    }

    // ---- final merge: 32 contributors x top-2 per row -> top-8 ----
    asm volatile("cp.async.wait_group 0;" ::: "memory");   // drain tail groups
    __syncthreads();                       // B stages dead; alias merge buffer
    float2* mbuf = reinterpret_cast<float2*>(smem + SM_B); // [64 rows][32]
#pragma unroll
    for (int mf = 0; mf < 4; ++mf)
#pragma unroll
        for (int h = 0; h < 2; ++h) {
            int row = mf * 16 + h * 8 + (lane >> 2);
            mbuf[row * 32 + w * 4 + q] = make_float2(tb1[mf][h], tb2[mf][h]);
        }
    __syncthreads();
    if (tid < MT) {
        float bs[8];
#pragma unroll
        for (int e = 0; e < 8; ++e) bs[e] = -FLT_MAX;
        for (int e = 0; e < 32; ++e) {
            float2 v = mbuf[tid * 32 + e];
            top8_ins(bs, v.x);
            top8_ins(bs, v.y);
        }
#pragma unroll
        for (int e = 0; e < 8; ++e)
            g_top8[m0 + tid][e] = (int)(__float_as_uint(bs[e]) & IDXMASK);
    }
}

// ---------------------------------------------------------------------------
// Refine + gather, CTA-per-row: warp c rescored candidate c exactly in fp32;
// block reduces, then 128 threads copy the winner row.
// ---------------------------------------------------------------------------
__global__ void __launch_bounds__(256)
refine_gather_kernel(const float* __restrict__ x,
                     const float* __restrict__ emb,
                     float* __restrict__ out) {
    __shared__ float sScore[8];
    __shared__ int   sCand[8];
    __shared__ int   sBest;

    const int row  = blockIdx.x;
    const int wid  = threadIdx.x >> 5;
    const int lane = threadIdx.x & 31;

    const int cand = g_top8[row][wid];
    const float4* xr = reinterpret_cast<const float4*>(x + (size_t)row * DIM);
    const float4* er = reinterpret_cast<const float4*>(emb + (size_t)cand * DIM);
    float d = 0.f;
#pragma unroll
    for (int j = 0; j < 4; ++j) {
        float4 xv = xr[lane + j * 32];
        float4 ev = er[lane + j * 32];
        d += xv.x * ev.x + xv.y * ev.y + xv.z * ev.z + xv.w * ev.w;
    }
#pragma unroll
    for (int o = 16; o; o >>= 1) d += __shfl_xor_sync(0xffffffffu, d, o);
    if (lane == 0) {
        sScore[wid] = d - 0.5f * g_e2[cand];
        sCand[wid]  = cand;
    }
    __syncthreads();
    if (threadIdx.x == 0) {
        float bs = sScore[0]; int bi = sCand[0];
#pragma unroll
        for (int c = 1; c < 8; ++c) {
            float s = sScore[c]; int ci = sCand[c];
            if (s > bs || (s == bs && ci < bi)) { bs = s; bi = ci; }
        }
        sBest = bi;
    }
    __syncthreads();
    const int bi = sBest;
    const float4* src = reinterpret_cast<const float4*>(emb + (size_t)bi * DIM);
    float4*       dst = reinterpret_cast<float4*>(out + (size_t)row * DIM);
    if (threadIdx.x < 128) dst[threadIdx.x] = src[threadIdx.x];
}

// ---------------------------------------------------------------------------
extern "C" void kernel_launch(void* const* d_in, const int* in_sizes, int n_in,
                              void* d_out, int out_size) {
    const float* x   = (const float*)d_in[0];
    const float* emb = (const float*)d_in[1];
    float*       out = (float*)d_out;

    cudaFuncSetAttribute(vq_main_kernel,
                         cudaFuncAttributeMaxDynamicSharedMemorySize, SMEM_TOTAL);

    cvt_e2_kernel<<<K_CODES / 8, 256>>>(emb);
    vq_main_kernel<<<M_TOTAL / MT, NTHR, SMEM_TOTAL>>>(x);
    refine_gather_kernel<<<M_TOTAL, 256>>>(x, emb, out);
}

// round 15
// speedup vs baseline: 1.0225x; 1.0225x over previous
#include <cuda_runtime.h>
#include <cuda_bf16.h>
#include <cstdint>
#include <cfloat>

// ---------------------------------------------------------------------------
// Problem constants
// ---------------------------------------------------------------------------
#define M_TOTAL 16384
#define K_CODES 8192
#define DIM     512
#define MT      64              // rows per CTA (2 CTAs/SM)
#define BN      256             // codes per chunk; warp tile 64x32
#define NCHUNK  (K_CODES / BN)  // 32
#define BK      32              // bf16 K per pipeline step (64 B/row)
#define KSTEPS  (DIM / BK)      // 16
#define NSTEPS  (NCHUNK * KSTEPS) // 512
#define NTHR    256
#define IDXMASK 0x1FFFu         // 13 bits: code index embedded in mantissa

// ---------------------------------------------------------------------------
// Scratch (static device arrays: allocation-free rule)
// ---------------------------------------------------------------------------
__device__ __nv_bfloat16 g_Ab[(size_t)M_TOTAL * DIM];   // bf16(x)   16 MB
__device__ __nv_bfloat16 g_Bb[(size_t)K_CODES * DIM];   // bf16(emb)  8 MB
__device__ float g_e2[K_CODES];
__device__ int   g_top8[M_TOTAL][8];

// ---------------------------------------------------------------------------
// Baseline-PTX helpers (no "a"-suffix arch features)
// ---------------------------------------------------------------------------
__device__ __forceinline__ uint32_t smem_u32(const void* p) {
    uint32_t a;
    asm("{ .reg .u64 t; cvta.to.shared.u64 t, %1; cvt.u32.u64 %0, t; }"
        : "=r"(a) : "l"(p));
    return a;
}

__device__ __forceinline__ void cp_async16(uint32_t dst, const void* src) {
    uint64_t g;
    asm("cvta.to.global.u64 %0, %1;" : "=l"(g) : "l"(src));
    asm volatile("cp.async.cg.shared.global [%0], [%1], 16;"
                 :: "r"(dst), "l"(g) : "memory");
}

// Pre-converted global address variant (no per-call cvta).
__device__ __forceinline__ void cp_async16g(uint32_t dst, uint64_t gsrc) {
    asm volatile("cp.async.cg.shared.global [%0], [%1], 16;"
                 :: "r"(dst), "l"(gsrc) : "memory");
}
#define CP_COMMIT() asm volatile("cp.async.commit_group;" ::: "memory")

__device__ __forceinline__ void ldmatrix_x4(uint32_t& r0, uint32_t& r1,
                                            uint32_t& r2, uint32_t& r3,
                                            uint32_t addr) {
    asm volatile("ldmatrix.sync.aligned.m8n8.x4.shared.b16 {%0,%1,%2,%3}, [%4];"
                 : "=r"(r0), "=r"(r1), "=r"(r2), "=r"(r3) : "r"(addr));
}

__device__ __forceinline__ void mma_bf16(float& d0, float& d1, float& d2, float& d3,
                                         uint32_t a0, uint32_t a1, uint32_t a2, uint32_t a3,
                                         uint32_t b0, uint32_t b1) {
    asm volatile(
        "mma.sync.aligned.m16n8k16.row.col.f32.bf16.bf16.f32 "
        "{%0,%1,%2,%3}, {%4,%5,%6,%7}, {%8,%9}, {%0,%1,%2,%3};"
        : "+f"(d0), "+f"(d1), "+f"(d2), "+f"(d3)
        : "r"(a0), "r"(a1), "r"(a2), "r"(a3), "r"(b0), "r"(b1));
}

// Embed code index in low 13 mantissa bits (single LOP3).
__device__ __forceinline__ float embed_idx(float s, uint32_t idx) {
    uint32_t r;
    asm("lop3.b32 %0, %1, %2, %3, 0xEA;"     // (a & b) | c
        : "=r"(r) : "r"(__float_as_uint(s)), "r"(~IDXMASK), "r"(idx));
    return __uint_as_float(r);
}

// Branchless top-2 (values carry their index).
__device__ __forceinline__ void top2f(float& b1, float& b2, float s) {
    float hi = fmaxf(b1, s);
    float lo = fminf(b1, s);
    b1 = hi;
    b2 = fmaxf(b2, lo);
}

// ---------------------------------------------------------------------------
// SMEM layout: A persistent 64 KB + B 3 stages x 16 KB -> 112 KB, 2 CTAs/SM.
// Each B stage = 8 warp-private slices of 2 KB (32 rows x 64 B).
// ---------------------------------------------------------------------------
#define SM_A       0                          // 64 rows x 1024 B
#define SM_B       65536
#define B_STAGE    16384
#define W_SLICE    2048
#define SMEM_TOTAL (SM_B + 3 * B_STAGE)       // 114688

// ---------------------------------------------------------------------------
// Fused kernel: g_Bb = bf16(emb), g_e2[k] = ||emb_k||^2 (one emb read pass)
// ---------------------------------------------------------------------------
__global__ void cvt_e2_kernel(const float* __restrict__ emb) {
    int row  = blockIdx.x * 8 + (threadIdx.x >> 5);
    int lane = threadIdx.x & 31;
    const float4* p = reinterpret_cast<const float4*>(emb + (size_t)row * DIM);
    __nv_bfloat162* o = reinterpret_cast<__nv_bfloat162*>(g_Bb) + (size_t)row * 256;
    float s = 0.f;
#pragma unroll
    for (int i = 0; i < 4; ++i) {
        int idx = lane + i * 32;
        float4 v = p[idx];
        s += v.x * v.x + v.y * v.y + v.z * v.z + v.w * v.w;
        o[idx * 2 + 0] = __floats2bfloat162_rn(v.x, v.y);
        o[idx * 2 + 1] = __floats2bfloat162_rn(v.z, v.w);
    }
#pragma unroll
    for (int off = 16; off; off >>= 1) s += __shfl_xor_sync(0xffffffffu, s, off);
    if (lane == 0) g_e2[row] = s;
}

// ---------------------------------------------------------------------------
// bf16 convert kernel for x
// ---------------------------------------------------------------------------
__global__ void cvt_x_kernel(const float* __restrict__ src) {
    size_t i = (size_t)blockIdx.x * 256 + threadIdx.x;   // float4 units
    float4 v = reinterpret_cast<const float4*>(src)[i];
    reinterpret_cast<__nv_bfloat162*>(g_Ab)[i * 2 + 0] = __floats2bfloat162_rn(v.x, v.y);
    reinterpret_cast<__nv_bfloat162*>(g_Ab)[i * 2 + 1] = __floats2bfloat162_rn(v.z, v.w);
}

// ---------------------------------------------------------------------------
// Top-8 insert on embedded-score floats (descending)
// ---------------------------------------------------------------------------
__device__ __forceinline__ void top8_ins(float* b, float s) {
    if (s <= b[7]) return;
    int p = 7;
#pragma unroll
    for (int t = 0; t < 7; ++t) {
        if (p > 0 && s > b[p - 1]) { b[p] = b[p - 1]; --p; }
    }
    b[p] = s;
}

// ---------------------------------------------------------------------------
// Main kernel: bf16 HMMA, warp tile 64x32, fully warp-private B pipelines.
// No bar.sync anywhere in the k-loop. (Proven R13 structure, unchanged.)
// ---------------------------------------------------------------------------
__global__ void __launch_bounds__(NTHR, 2)
vq_main_kernel() {
    extern __shared__ char smem[];
    uint32_t sb = smem_u32(smem);

    const int tid  = threadIdx.x;
    const int lane = tid & 31;
    const int w    = tid >> 5;     // warp 0..7: owns codes [w*32, w*32+32) per chunk
    const int q    = lane & 3;
    const int m0   = blockIdx.x * MT;

    // ---- Prologue: persistent A (cooperative; part of group G0) ----
#pragma unroll
    for (int j = 0; j < 16; ++j) {            // 4096 16B chunks
        int id = tid + j * 256;
        int row = id >> 6, c = id & 63;       // 64 chunks per 1024B row
        const void* src = g_Ab + (size_t)(m0 + row) * DIM + c * 8;
        uint32_t dst = sb + SM_A + row * 1024 + (c >> 3) * 128
                       + (((c & 7) ^ (row & 7)) * 16);
        cp_async16(dst, src);
    }

    // Per-thread B-fill constants. Thread covers rows row0+8j (j=0..3), chunk c0.
    // swz is j-invariant: ((row0+8j)>>1)&3 == (row0>>1)&3.
    const int row0 = lane >> 2;               // 0..7
    const int c0   = lane & 3;
    uint64_t gB;
    asm("cvta.to.global.u64 %0, %1;" : "=l"(gB) : "l"(g_Bb));
    const uint64_t pbase = gB
        + (uint32_t)(((w * 32 + row0) * 512 + c0 * 8) * 2);           // bytes
    const uint32_t d0 = (uint32_t)(w * W_SLICE + row0 * 64
                                   + ((c0 ^ ((row0 >> 1) & 3)) * 16));

    // Fill gs=0 (group G0, with A) and gs=1 (G1). gs: ch=gs>>4, st=gs&15.
    {
        uint32_t fb = sb + SM_B + 0 * B_STAGE + d0;
#pragma unroll
        for (int j = 0; j < 4; ++j) cp_async16g(fb + j * 512, pbase + j * 8192);
        CP_COMMIT();
    }
    {
        uint32_t fb = sb + SM_B + 1 * B_STAGE + d0;
#pragma unroll
        for (int j = 0; j < 4; ++j) cp_async16g(fb + j * 512, pbase + 64 + j * 8192);
        CP_COMMIT();
    }

    asm volatile("cp.async.wait_group 1;" ::: "memory");   // G0: A + slice0
    __syncthreads();                                       // A visible to all

    // per-thread running top-2 (embedded-index floats) for 8 row-slots [mf][h]
    float tb1[4][2], tb2[4][2];
#pragma unroll
    for (int a = 0; a < 4; ++a)
#pragma unroll
        for (int b = 0; b < 2; ++b) { tb1[a][b] = -FLT_MAX; tb2[a][b] = -FLT_MAX; }

    int sr = 0;                                // gs % 3
#pragma unroll 1
    for (int ch = 0; ch < NCHUNK; ++ch) {
        const int n0 = ch * BN;

        float acc[4][4][4];
#pragma unroll
        for (int a = 0; a < 4; ++a)
#pragma unroll
            for (int b = 0; b < 4; ++b)
#pragma unroll
                for (int c = 0; c < 4; ++c) acc[a][b][c] = 0.f;

#pragma unroll 1
        for (int st = 0; st < KSTEPS; ++st) {
            const int gs = ch * KSTEPS + st;

            // ---- A fragments for sub 0 (persistent smem; no dependency) ----
            uint32_t afr[4][4];
#pragma unroll
            for (int mf = 0; mf < 4; ++mf) {
                int row = mf * 16 + (lane & 15);
                int cA  = (st * 2) * 2 + (lane >> 4);   // k16 = st*2
                uint32_t addr = sb + SM_A + row * 1024 + (cA >> 3) * 128
                                + (((cA & 7) ^ (row & 7)) * 16);
                ldmatrix_x4(afr[mf][0], afr[mf][1], afr[mf][2], afr[mf][3], addr);
            }

            // Refill stage (gs+2)%3 BEFORE the wait (read-complete at gs-1).
            const int sf = (sr >= 1) ? (sr - 1) : 2;
            if (gs + 2 < NSTEPS) {
                const int g2 = gs + 2;
                uint64_t src = pbase
                    + (uint32_t)(((g2 >> 4) << 18) + ((g2 & 15) << 6));
                uint32_t fb = sb + SM_B + sf * B_STAGE + d0;
#pragma unroll
                for (int j = 0; j < 4; ++j)
                    cp_async16g(fb + j * 512, src + j * 8192);
                CP_COMMIT();
            } else {
                CP_COMMIT();           // keep group arithmetic uniform
            }

            // Own fill of stage gs%3 complete (newest group stays in flight).
            asm volatile("cp.async.wait_group 1;" ::: "memory");

            const uint32_t bb = sb + SM_B + sr * B_STAGE + w * W_SLICE;

#pragma unroll
            for (int sub = 0; sub < 2; ++sub) {        // 2 x k16 per BK=32
                if (sub == 1) {
                    // A fragments for sub 1 (reuse afr registers)
#pragma unroll
                    for (int mf = 0; mf < 4; ++mf) {
                        int row = mf * 16 + (lane & 15);
                        int cA  = (st * 2 + 1) * 2 + (lane >> 4);
                        uint32_t addr = sb + SM_A + row * 1024 + (cA >> 3) * 128
                                        + (((cA & 7) ^ (row & 7)) * 16);
                        ldmatrix_x4(afr[mf][0], afr[mf][1],
                                    afr[mf][2], afr[mf][3], addr);
                    }
                }
                // ---- B fragments: 4 n-frags (8 codes each) = 2 ldmatrix.x4 ----
                uint32_t bfr[4][2];
#pragma unroll
                for (int p = 0; p < 2; ++p) {
                    int mi   = lane >> 3;
                    int noff = (mi >> 1) * 8;
                    int kc   = mi & 1;
                    int rloc = p * 16 + noff + (lane & 7);   // 0..31
                    int c    = sub * 2 + kc;
                    uint32_t addr = bb + rloc * 64
                                    + ((c ^ ((rloc >> 1) & 3)) * 16);
                    ldmatrix_x4(bfr[p*2][0], bfr[p*2][1],
                                bfr[p*2+1][0], bfr[p*2+1][1], addr);
                }
#pragma unroll
                for (int mf = 0; mf < 4; ++mf)
#pragma unroll
                    for (int nf = 0; nf < 4; ++nf)
                        mma_bf16(acc[mf][nf][0], acc[mf][nf][1],
                                 acc[mf][nf][2], acc[mf][nf][3],
                                 afr[mf][0], afr[mf][1], afr[mf][2], afr[mf][3],
                                 bfr[nf][0], bfr[nf][1]);
            }
            sr = (sr == 2) ? 0 : sr + 1;
        }

        // ---- epilogue: branchless embedded-index top-2 (no barriers) ----
        float e2h[8];
#pragma unroll
        for (int nf = 0; nf < 4; ++nf) {
            float2 p = *reinterpret_cast<const float2*>(
                &g_e2[n0 + w * 32 + nf * 8 + q * 2]);
            e2h[nf * 2] = 0.5f * p.x; e2h[nf * 2 + 1] = 0.5f * p.y;
        }
#pragma unroll
        for (int mf = 0; mf < 4; ++mf)
#pragma unroll
            for (int h = 0; h < 2; ++h)
#pragma unroll
                for (int nf = 0; nf < 4; ++nf) {
                    uint32_t cloc = (uint32_t)(n0 + w * 32 + nf * 8 + q * 2);
                    float s0 = embed_idx(acc[mf][nf][h*2+0] - e2h[nf*2+0], cloc);
                    float s1 = embed_idx(acc[mf][nf][h*2+1] - e2h[nf*2+1], cloc + 1);
                    top2f(tb1[mf][h], tb2[mf][h], s0);
                    top2f(tb1[mf][h], tb2[mf][h], s1);
                }
    }

    // ---- final merge: 32 contributors x top-2 per row -> top-8 ----
    asm volatile("cp.async.wait_group 0;" ::: "memory");   // drain tail groups
    __syncthreads();                       // B stages dead; alias merge buffer
    float2* mbuf = reinterpret_cast<float2*>(smem + SM_B); // [64 rows][32]
#pragma unroll
    for (int mf = 0; mf < 4; ++mf)
#pragma unroll
        for (int h = 0; h < 2; ++h) {
            int row = mf * 16 + h * 8 + (lane >> 2);
            mbuf[row * 32 + w * 4 + q] = make_float2(tb1[mf][h], tb2[mf][h]);
        }
    __syncthreads();
    if (tid < MT) {
        float bs[8];
#pragma unroll
        for (int e = 0; e < 8; ++e) bs[e] = -FLT_MAX;
        for (int e = 0; e < 32; ++e) {
            float2 v = mbuf[tid * 32 + e];
            top8_ins(bs, v.x);
            top8_ins(bs, v.y);
        }
#pragma unroll
        for (int e = 0; e < 8; ++e)
            g_top8[m0 + tid][e] = (int)(__float_as_uint(bs[e]) & IDXMASK);
    }
}

// ---------------------------------------------------------------------------
// Refine + gather, CTA-per-row: warp c rescored candidate c exactly in fp32;
// block reduces, then 128 threads copy the winner row.
// ---------------------------------------------------------------------------
__global__ void __launch_bounds__(256)
refine_gather_kernel(const float* __restrict__ x,
                     const float* __restrict__ emb,
                     float* __restrict__ out) {
    __shared__ float sScore[8];
    __shared__ int   sCand[8];
    __shared__ int   sBest;

    const int row  = blockIdx.x;
    const int wid  = threadIdx.x >> 5;
    const int lane = threadIdx.x & 31;

    const int cand = g_top8[row][wid];
    const float4* xr = reinterpret_cast<const float4*>(x + (size_t)row * DIM);
    const float4* er = reinterpret_cast<const float4*>(emb + (size_t)cand * DIM);
    float d = 0.f;
#pragma unroll
    for (int j = 0; j < 4; ++j) {
        float4 xv = xr[lane + j * 32];
        float4 ev = er[lane + j * 32];
        d += xv.x * ev.x + xv.y * ev.y + xv.z * ev.z + xv.w * ev.w;
    }
#pragma unroll
    for (int o = 16; o; o >>= 1) d += __shfl_xor_sync(0xffffffffu, d, o);
    if (lane == 0) {
        sScore[wid] = d - 0.5f * g_e2[cand];
        sCand[wid]  = cand;
    }
    __syncthreads();
    if (threadIdx.x == 0) {
        float bs = sScore[0]; int bi = sCand[0];
#pragma unroll
        for (int c = 1; c < 8; ++c) {
            float s = sScore[c]; int ci = sCand[c];
            if (s > bs || (s == bs && ci < bi)) { bs = s; bi = ci; }
        }
        sBest = bi;
    }
    __syncthreads();
    const int bi = sBest;
    const float4* src = reinterpret_cast<const float4*>(emb + (size_t)bi * DIM);
    float4*       dst = reinterpret_cast<float4*>(out + (size_t)row * DIM);
    if (threadIdx.x < 128) dst[threadIdx.x] = src[threadIdx.x];
}

// ---------------------------------------------------------------------------
extern "C" void kernel_launch(void* const* d_in, const int* in_sizes, int n_in,
                              void* d_out, int out_size) {
    const float* x   = (const float*)d_in[0];
    const float* emb = (const float*)d_in[1];
    float*       out = (float*)d_out;

    cudaFuncSetAttribute(vq_main_kernel,
                         cudaFuncAttributeMaxDynamicSharedMemorySize, SMEM_TOTAL);

    cvt_e2_kernel<<<K_CODES / 8, 256>>>(emb);
    cvt_x_kernel<<<(M_TOTAL * DIM / 4) / 256, 256>>>(x);
    vq_main_kernel<<<M_TOTAL / MT, NTHR, SMEM_TOTAL>>>();
    refine_gather_kernel<<<M_TOTAL, 256>>>(x, emb, out);
}

// round 16
// speedup vs baseline: 1.0845x; 1.0607x over previous
#include <cuda_runtime.h>
#include <cuda_bf16.h>
#include <cstdint>
#include <cfloat>

// ---------------------------------------------------------------------------
// Problem constants
// ---------------------------------------------------------------------------
#define M_TOTAL 16384
#define K_CODES 8192
#define DIM     512
#define MT      64              // rows per CTA (2 CTAs/SM)
#define BN      256             // codes per chunk; warp tile 64x32
#define NCHUNK  (K_CODES / BN)  // 32
#define BK      32              // bf16 K per pipeline step (64 B/row)
#define KSTEPS  (DIM / BK)      // 16
#define NSTEPS  (NCHUNK * KSTEPS) // 512
#define NTHR    256
#define IDXMASK 0x1FFFu         // 13 bits: code index embedded in mantissa

// ---------------------------------------------------------------------------
// Scratch (static device arrays: allocation-free rule)
// ---------------------------------------------------------------------------
__device__ __nv_bfloat16 g_Ab[(size_t)M_TOTAL * DIM];   // bf16(x)   16 MB
__device__ __nv_bfloat16 g_Bb[(size_t)K_CODES * DIM];   // bf16(emb)  8 MB
__device__ float g_e2[K_CODES];
__device__ int4  g_top4[M_TOTAL];

// ---------------------------------------------------------------------------
// Baseline-PTX helpers (no "a"-suffix arch features)
// ---------------------------------------------------------------------------
__device__ __forceinline__ uint32_t smem_u32(const void* p) {
    uint32_t a;
    asm("{ .reg .u64 t; cvta.to.shared.u64 t, %1; cvt.u32.u64 %0, t; }"
        : "=r"(a) : "l"(p));
    return a;
}

__device__ __forceinline__ void cp_async16(uint32_t dst, const void* src) {
    uint64_t g;
    asm("cvta.to.global.u64 %0, %1;" : "=l"(g) : "l"(src));
    asm volatile("cp.async.cg.shared.global [%0], [%1], 16;"
                 :: "r"(dst), "l"(g) : "memory");
}

// Pre-converted global address variant (no per-call cvta).
__device__ __forceinline__ void cp_async16g(uint32_t dst, uint64_t gsrc) {
    asm volatile("cp.async.cg.shared.global [%0], [%1], 16;"
                 :: "r"(dst), "l"(gsrc) : "memory");
}
#define CP_COMMIT() asm volatile("cp.async.commit_group;" ::: "memory")

__device__ __forceinline__ void ldmatrix_x4(uint32_t& r0, uint32_t& r1,
                                            uint32_t& r2, uint32_t& r3,
                                            uint32_t addr) {
    asm volatile("ldmatrix.sync.aligned.m8n8.x4.shared.b16 {%0,%1,%2,%3}, [%4];"
                 : "=r"(r0), "=r"(r1), "=r"(r2), "=r"(r3) : "r"(addr));
}

__device__ __forceinline__ void mma_bf16(float& d0, float& d1, float& d2, float& d3,
                                         uint32_t a0, uint32_t a1, uint32_t a2, uint32_t a3,
                                         uint32_t b0, uint32_t b1) {
    asm volatile(
        "mma.sync.aligned.m16n8k16.row.col.f32.bf16.bf16.f32 "
        "{%0,%1,%2,%3}, {%4,%5,%6,%7}, {%8,%9}, {%0,%1,%2,%3};"
        : "+f"(d0), "+f"(d1), "+f"(d2), "+f"(d3)
        : "r"(a0), "r"(a1), "r"(a2), "r"(a3), "r"(b0), "r"(b1));
}

// Embed code index in low 13 mantissa bits (single LOP3).
__device__ __forceinline__ float embed_idx(float s, uint32_t idx) {
    uint32_t r;
    asm("lop3.b32 %0, %1, %2, %3, 0xEA;"     // (a & b) | c
        : "=r"(r) : "r"(__float_as_uint(s)), "r"(~IDXMASK), "r"(idx));
    return __uint_as_float(r);
}

// Branchless top-2 (values carry their index).
__device__ __forceinline__ void top2f(float& b1, float& b2, float s) {
    float hi = fmaxf(b1, s);
    float lo = fminf(b1, s);
    b1 = hi;
    b2 = fmaxf(b2, lo);
}

// ---------------------------------------------------------------------------
// SMEM layout: A persistent 64 KB + B 3 stages x 16 KB -> 112 KB, 2 CTAs/SM.
// Each B stage = 8 warp-private slices of 2 KB (32 rows x 64 B).
// ---------------------------------------------------------------------------
#define SM_A       0                          // 64 rows x 1024 B
#define SM_B       65536
#define B_STAGE    16384
#define W_SLICE    2048
#define SMEM_TOTAL (SM_B + 3 * B_STAGE)       // 114688

// ---------------------------------------------------------------------------
// Fused kernel: g_Bb = bf16(emb), g_e2[k] = ||emb_k||^2 (one emb read pass)
// ---------------------------------------------------------------------------
__global__ void cvt_e2_kernel(const float* __restrict__ emb) {
    int row  = blockIdx.x * 8 + (threadIdx.x >> 5);
    int lane = threadIdx.x & 31;
    const float4* p = reinterpret_cast<const float4*>(emb + (size_t)row * DIM);
    __nv_bfloat162* o = reinterpret_cast<__nv_bfloat162*>(g_Bb) + (size_t)row * 256;
    float s = 0.f;
#pragma unroll
    for (int i = 0; i < 4; ++i) {
        int idx = lane + i * 32;
        float4 v = p[idx];
        s += v.x * v.x + v.y * v.y + v.z * v.z + v.w * v.w;
        o[idx * 2 + 0] = __floats2bfloat162_rn(v.x, v.y);
        o[idx * 2 + 1] = __floats2bfloat162_rn(v.z, v.w);
    }
#pragma unroll
    for (int off = 16; off; off >>= 1) s += __shfl_xor_sync(0xffffffffu, s, off);
    if (lane == 0) g_e2[row] = s;
}

// ---------------------------------------------------------------------------
// bf16 convert kernel for x
// ---------------------------------------------------------------------------
__global__ void cvt_x_kernel(const float* __restrict__ src) {
    size_t i = (size_t)blockIdx.x * 256 + threadIdx.x;   // float4 units
    float4 v = reinterpret_cast<const float4*>(src)[i];
    reinterpret_cast<__nv_bfloat162*>(g_Ab)[i * 2 + 0] = __floats2bfloat162_rn(v.x, v.y);
    reinterpret_cast<__nv_bfloat162*>(g_Ab)[i * 2 + 1] = __floats2bfloat162_rn(v.z, v.w);
}

// ---------------------------------------------------------------------------
// Top-4 insert on embedded-score floats (descending)
// ---------------------------------------------------------------------------
__device__ __forceinline__ void top4_ins(float* b, float s) {
    if (s <= b[3]) return;
    int p = 3;
#pragma unroll
    for (int t = 0; t < 3; ++t) {
        if (p > 0 && s > b[p - 1]) { b[p] = b[p - 1]; --p; }
    }
    b[p] = s;
}

// ---------------------------------------------------------------------------
// Main kernel: bf16 HMMA, warp tile 64x32, fully warp-private B pipelines.
// No bar.sync anywhere in the k-loop. (Proven R13 structure, unchanged.)
// ---------------------------------------------------------------------------
__global__ void __launch_bounds__(NTHR, 2)
vq_main_kernel() {
    extern __shared__ char smem[];
    uint32_t sb = smem_u32(smem);

    const int tid  = threadIdx.x;
    const int lane = tid & 31;
    const int w    = tid >> 5;     // warp 0..7: owns codes [w*32, w*32+32) per chunk
    const int q    = lane & 3;
    const int m0   = blockIdx.x * MT;

    // ---- Prologue: persistent A (cooperative; part of group G0) ----
#pragma unroll
    for (int j = 0; j < 16; ++j) {            // 4096 16B chunks
        int id = tid + j * 256;
        int row = id >> 6, c = id & 63;       // 64 chunks per 1024B row
        const void* src = g_Ab + (size_t)(m0 + row) * DIM + c * 8;
        uint32_t dst = sb + SM_A + row * 1024 + (c >> 3) * 128
                       + (((c & 7) ^ (row & 7)) * 16);
        cp_async16(dst, src);
    }

    // Per-thread B-fill constants. Thread covers rows row0+8j (j=0..3), chunk c0.
    const int row0 = lane >> 2;               // 0..7
    const int c0   = lane & 3;
    uint64_t gB;
    asm("cvta.to.global.u64 %0, %1;" : "=l"(gB) : "l"(g_Bb));
    const uint64_t pbase = gB
        + (uint32_t)(((w * 32 + row0) * 512 + c0 * 8) * 2);           // bytes
    const uint32_t d0 = (uint32_t)(w * W_SLICE + row0 * 64
                                   + ((c0 ^ ((row0 >> 1) & 3)) * 16));

    // Fill gs=0 (group G0, with A) and gs=1 (G1). gs: ch=gs>>4, st=gs&15.
    {
        uint32_t fb = sb + SM_B + 0 * B_STAGE + d0;
#pragma unroll
        for (int j = 0; j < 4; ++j) cp_async16g(fb + j * 512, pbase + j * 8192);
        CP_COMMIT();
    }
    {
        uint32_t fb = sb + SM_B + 1 * B_STAGE + d0;
#pragma unroll
        for (int j = 0; j < 4; ++j) cp_async16g(fb + j * 512, pbase + 64 + j * 8192);
        CP_COMMIT();
    }

    asm volatile("cp.async.wait_group 1;" ::: "memory");   // G0: A + slice0
    __syncthreads();                                       // A visible to all

    // per-thread running top-2 (embedded-index floats) for 8 row-slots [mf][h]
    float tb1[4][2], tb2[4][2];
#pragma unroll
    for (int a = 0; a < 4; ++a)
#pragma unroll
        for (int b = 0; b < 2; ++b) { tb1[a][b] = -FLT_MAX; tb2[a][b] = -FLT_MAX; }

    int sr = 0;                                // gs % 3
#pragma unroll 1
    for (int ch = 0; ch < NCHUNK; ++ch) {
        const int n0 = ch * BN;

        float acc[4][4][4];
#pragma unroll
        for (int a = 0; a < 4; ++a)
#pragma unroll
            for (int b = 0; b < 4; ++b)
#pragma unroll
                for (int c = 0; c < 4; ++c) acc[a][b][c] = 0.f;

#pragma unroll 1
        for (int st = 0; st < KSTEPS; ++st) {
            const int gs = ch * KSTEPS + st;

            // ---- A fragments for sub 0 (persistent smem; no dependency) ----
            uint32_t afr[4][4];
#pragma unroll
            for (int mf = 0; mf < 4; ++mf) {
                int row = mf * 16 + (lane & 15);
                int cA  = (st * 2) * 2 + (lane >> 4);   // k16 = st*2
                uint32_t addr = sb + SM_A + row * 1024 + (cA >> 3) * 128
                                + (((cA & 7) ^ (row & 7)) * 16);
                ldmatrix_x4(afr[mf][0], afr[mf][1], afr[mf][2], afr[mf][3], addr);
            }

            // Refill stage (gs+2)%3 BEFORE the wait (read-complete at gs-1).
            const int sf = (sr >= 1) ? (sr - 1) : 2;
            if (gs + 2 < NSTEPS) {
                const int g2 = gs + 2;
                uint64_t src = pbase
                    + (uint32_t)(((g2 >> 4) << 18) + ((g2 & 15) << 6));
                uint32_t fb = sb + SM_B + sf * B_STAGE + d0;
#pragma unroll
                for (int j = 0; j < 4; ++j)
                    cp_async16g(fb + j * 512, src + j * 8192);
                CP_COMMIT();
            } else {
                CP_COMMIT();           // keep group arithmetic uniform
            }

            // Own fill of stage gs%3 complete (newest group stays in flight).
            asm volatile("cp.async.wait_group 1;" ::: "memory");

            const uint32_t bb = sb + SM_B + sr * B_STAGE + w * W_SLICE;

#pragma unroll
            for (int sub = 0; sub < 2; ++sub) {        // 2 x k16 per BK=32
                if (sub == 1) {
                    // A fragments for sub 1 (reuse afr registers)
#pragma unroll
                    for (int mf = 0; mf < 4; ++mf) {
                        int row = mf * 16 + (lane & 15);
                        int cA  = (st * 2 + 1) * 2 + (lane >> 4);
                        uint32_t addr = sb + SM_A + row * 1024 + (cA >> 3) * 128
                                        + (((cA & 7) ^ (row & 7)) * 16);
                        ldmatrix_x4(afr[mf][0], afr[mf][1],
                                    afr[mf][2], afr[mf][3], addr);
                    }
                }
                // ---- B fragments: 4 n-frags (8 codes each) = 2 ldmatrix.x4 ----
                uint32_t bfr[4][2];
#pragma unroll
                for (int p = 0; p < 2; ++p) {
                    int mi   = lane >> 3;
                    int noff = (mi >> 1) * 8;
                    int kc   = mi & 1;
                    int rloc = p * 16 + noff + (lane & 7);   // 0..31
                    int c    = sub * 2 + kc;
                    uint32_t addr = bb + rloc * 64
                                    + ((c ^ ((rloc >> 1) & 3)) * 16);
                    ldmatrix_x4(bfr[p*2][0], bfr[p*2][1],
                                bfr[p*2+1][0], bfr[p*2+1][1], addr);
                }
#pragma unroll
                for (int mf = 0; mf < 4; ++mf)
#pragma unroll
                    for (int nf = 0; nf < 4; ++nf)
                        mma_bf16(acc[mf][nf][0], acc[mf][nf][1],
                                 acc[mf][nf][2], acc[mf][nf][3],
                                 afr[mf][0], afr[mf][1], afr[mf][2], afr[mf][3],
                                 bfr[nf][0], bfr[nf][1]);
            }
            sr = (sr == 2) ? 0 : sr + 1;
        }

        // ---- epilogue: branchless embedded-index top-2 (no barriers) ----
        float e2h[8];
#pragma unroll
        for (int nf = 0; nf < 4; ++nf) {
            float2 p = *reinterpret_cast<const float2*>(
                &g_e2[n0 + w * 32 + nf * 8 + q * 2]);
            e2h[nf * 2] = 0.5f * p.x; e2h[nf * 2 + 1] = 0.5f * p.y;
        }
#pragma unroll
        for (int mf = 0; mf < 4; ++mf)
#pragma unroll
            for (int h = 0; h < 2; ++h)
#pragma unroll
                for (int nf = 0; nf < 4; ++nf) {
                    uint32_t cloc = (uint32_t)(n0 + w * 32 + nf * 8 + q * 2);
                    float s0 = embed_idx(acc[mf][nf][h*2+0] - e2h[nf*2+0], cloc);
                    float s1 = embed_idx(acc[mf][nf][h*2+1] - e2h[nf*2+1], cloc + 1);
                    top2f(tb1[mf][h], tb2[mf][h], s0);
                    top2f(tb1[mf][h], tb2[mf][h], s1);
                }
    }

    // ---- final merge: 32 contributors x top-2 per row -> top-4 ----
    asm volatile("cp.async.wait_group 0;" ::: "memory");   // drain tail groups
    __syncthreads();                       // B stages dead; alias merge buffer
    float2* mbuf = reinterpret_cast<float2*>(smem + SM_B); // [64 rows][32]
#pragma unroll
    for (int mf = 0; mf < 4; ++mf)
#pragma unroll
        for (int h = 0; h < 2; ++h) {
            int row = mf * 16 + h * 8 + (lane >> 2);
            mbuf[row * 32 + w * 4 + q] = make_float2(tb1[mf][h], tb2[mf][h]);
        }
    __syncthreads();
    if (tid < MT) {
        float bs[4];
#pragma unroll
        for (int e = 0; e < 4; ++e) bs[e] = -FLT_MAX;
        for (int e = 0; e < 32; ++e) {
            float2 v = mbuf[tid * 32 + e];
            top4_ins(bs, v.x);
            top4_ins(bs, v.y);
        }
        g_top4[m0 + tid] = make_int4(
            (int)(__float_as_uint(bs[0]) & IDXMASK),
            (int)(__float_as_uint(bs[1]) & IDXMASK),
            (int)(__float_as_uint(bs[2]) & IDXMASK),
            (int)(__float_as_uint(bs[3]) & IDXMASK));
    }
}

// ---------------------------------------------------------------------------
// Refine + gather, warp-per-row (R13 structure): exact fp32 re-score of the
// top-4 candidates, copy the winner row.
// ---------------------------------------------------------------------------
__global__ void refine_gather_kernel(const float* __restrict__ x,
                                     const float* __restrict__ emb,
                                     float* __restrict__ out) {
    int row  = (blockIdx.x * blockDim.x + threadIdx.x) >> 5;
    int lane = threadIdx.x & 31;
    int4 cnd = g_top4[row];
    int cand[4] = {cnd.x, cnd.y, cnd.z, cnd.w};

    const float4* xr = reinterpret_cast<const float4*>(x + (size_t)row * DIM);
    float d[4] = {0.f, 0.f, 0.f, 0.f};
#pragma unroll
    for (int j = 0; j < 4; ++j) {
        float4 xv = xr[lane + j * 32];
#pragma unroll
        for (int c = 0; c < 4; ++c) {
            const float4* er = reinterpret_cast<const float4*>(
                emb + (size_t)cand[c] * DIM);
            float4 e = er[lane + j * 32];
            d[c] += xv.x * e.x + xv.y * e.y + xv.z * e.z + xv.w * e.w;
        }
    }
#pragma unroll
    for (int o = 16; o; o >>= 1)
#pragma unroll
        for (int c = 0; c < 4; ++c)
            d[c] += __shfl_xor_sync(0xffffffffu, d[c], o);

    float bs = d[0] - 0.5f * g_e2[cand[0]];
    int   bi = cand[0];
#pragma unroll
    for (int c = 1; c < 4; ++c) {
        float s = d[c] - 0.5f * g_e2[cand[c]];
        if (s > bs || (s == bs && cand[c] < bi)) { bs = s; bi = cand[c]; }
    }

    const float4* src = reinterpret_cast<const float4*>(emb + (size_t)bi * DIM);
    float4*       dst = reinterpret_cast<float4*>(out + (size_t)row * DIM);
#pragma unroll
    for (int j = 0; j < 4; ++j) dst[lane + j * 32] = src[lane + j * 32];
}

// ---------------------------------------------------------------------------
extern "C" void kernel_launch(void* const* d_in, const int* in_sizes, int n_in,
                              void* d_out, int out_size) {
    const float* x   = (const float*)d_in[0];
    const float* emb = (const float*)d_in[1];
    float*       out = (float*)d_out;

    cudaFuncSetAttribute(vq_main_kernel,
                         cudaFuncAttributeMaxDynamicSharedMemorySize, SMEM_TOTAL);

    cvt_e2_kernel<<<K_CODES / 8, 256>>>(emb);
    cvt_x_kernel<<<(M_TOTAL * DIM / 4) / 256, 256>>>(x);
    vq_main_kernel<<<M_TOTAL / MT, NTHR, SMEM_TOTAL>>>();
    refine_gather_kernel<<<M_TOTAL / 8, 256>>>(x, emb, out);
}

// round 17
// speedup vs baseline: 1.0881x; 1.0032x over previous
#include <cuda_runtime.h>
#include <cuda_bf16.h>
#include <cstdint>
#include <cfloat>

// ---------------------------------------------------------------------------
// Problem constants
// ---------------------------------------------------------------------------
#define M_TOTAL 16384
#define K_CODES 8192
#define DIM     512
#define MT      64              // rows per CTA (2 CTAs/SM)
#define BN      256             // codes per chunk; warp tile 64x32
#define NCHUNK  (K_CODES / BN)  // 32
#define BK      32              // bf16 K per pipeline step (64 B/row)
#define KSTEPS  (DIM / BK)      // 16
#define NSTEPS  (NCHUNK * KSTEPS) // 512
#define NTHR    256
#define IDXMASK 0x1FFFu         // 13 bits: code index embedded in mantissa

// ---------------------------------------------------------------------------
// Scratch (static device arrays: allocation-free rule)
// ---------------------------------------------------------------------------
__device__ __nv_bfloat16 g_Ab[(size_t)M_TOTAL * DIM];   // bf16(x)   16 MB
__device__ __nv_bfloat16 g_Bb[(size_t)K_CODES * DIM];   // bf16(emb)  8 MB
__device__ float g_e2[K_CODES];
__device__ int4  g_top4[M_TOTAL];

// ---------------------------------------------------------------------------
// Baseline-PTX helpers (no "a"-suffix arch features)
// ---------------------------------------------------------------------------
__device__ __forceinline__ uint32_t smem_u32(const void* p) {
    uint32_t a;
    asm("{ .reg .u64 t; cvta.to.shared.u64 t, %1; cvt.u32.u64 %0, t; }"
        : "=r"(a) : "l"(p));
    return a;
}

__device__ __forceinline__ void cp_async16(uint32_t dst, const void* src) {
    uint64_t g;
    asm("cvta.to.global.u64 %0, %1;" : "=l"(g) : "l"(src));
    asm volatile("cp.async.cg.shared.global [%0], [%1], 16;"
                 :: "r"(dst), "l"(g) : "memory");
}

__device__ __forceinline__ void cp_async16g(uint32_t dst, uint64_t gsrc) {
    asm volatile("cp.async.cg.shared.global [%0], [%1], 16;"
                 :: "r"(dst), "l"(gsrc) : "memory");
}
#define CP_COMMIT() asm volatile("cp.async.commit_group;" ::: "memory")

__device__ __forceinline__ void ldmatrix_x4(uint32_t& r0, uint32_t& r1,
                                            uint32_t& r2, uint32_t& r3,
                                            uint32_t addr) {
    asm volatile("ldmatrix.sync.aligned.m8n8.x4.shared.b16 {%0,%1,%2,%3}, [%4];"
                 : "=r"(r0), "=r"(r1), "=r"(r2), "=r"(r3) : "r"(addr));
}

__device__ __forceinline__ void mma_bf16(float& d0, float& d1, float& d2, float& d3,
                                         uint32_t a0, uint32_t a1, uint32_t a2, uint32_t a3,
                                         uint32_t b0, uint32_t b1) {
    asm volatile(
        "mma.sync.aligned.m16n8k16.row.col.f32.bf16.bf16.f32 "
        "{%0,%1,%2,%3}, {%4,%5,%6,%7}, {%8,%9}, {%0,%1,%2,%3};"
        : "+f"(d0), "+f"(d1), "+f"(d2), "+f"(d3)
        : "r"(a0), "r"(a1), "r"(a2), "r"(a3), "r"(b0), "r"(b1));
}

// Embed code index in low 13 mantissa bits (single LOP3).
__device__ __forceinline__ float embed_idx(float s, uint32_t idx) {
    uint32_t r;
    asm("lop3.b32 %0, %1, %2, %3, 0xEA;"     // (a & b) | c
        : "=r"(r) : "r"(__float_as_uint(s)), "r"(~IDXMASK), "r"(idx));
    return __uint_as_float(r);
}

// Branchless top-2 (values carry their index).
__device__ __forceinline__ void top2f(float& b1, float& b2, float s) {
    float hi = fmaxf(b1, s);
    float lo = fminf(b1, s);
    b1 = hi;
    b2 = fmaxf(b2, lo);
}

// ---------------------------------------------------------------------------
// SMEM layout: A persistent 64 KB + B 3 stages x 16 KB -> 112 KB, 2 CTAs/SM.
// Each B stage = 8 warp-private slices of 2 KB (32 rows x 64 B).
// ---------------------------------------------------------------------------
#define SM_A       0                          // 64 rows x 1024 B
#define SM_B       65536
#define B_STAGE    16384
#define W_SLICE    2048
#define SMEM_TOTAL (SM_B + 3 * B_STAGE)       // 114688

// ---------------------------------------------------------------------------
// Fused kernel: g_Bb = bf16(emb), g_e2[k] = ||emb_k||^2 (one emb read pass)
// ---------------------------------------------------------------------------
__global__ void cvt_e2_kernel(const float* __restrict__ emb) {
    int row  = blockIdx.x * 8 + (threadIdx.x >> 5);
    int lane = threadIdx.x & 31;
    const float4* p = reinterpret_cast<const float4*>(emb + (size_t)row * DIM);
    __nv_bfloat162* o = reinterpret_cast<__nv_bfloat162*>(g_Bb) + (size_t)row * 256;
    float s = 0.f;
#pragma unroll
    for (int i = 0; i < 4; ++i) {
        int idx = lane + i * 32;
        float4 v = p[idx];
        s += v.x * v.x + v.y * v.y + v.z * v.z + v.w * v.w;
        o[idx * 2 + 0] = __floats2bfloat162_rn(v.x, v.y);
        o[idx * 2 + 1] = __floats2bfloat162_rn(v.z, v.w);
    }
#pragma unroll
    for (int off = 16; off; off >>= 1) s += __shfl_xor_sync(0xffffffffu, s, off);
    if (lane == 0) g_e2[row] = s;
}

// ---------------------------------------------------------------------------
// bf16 convert kernel for x
// ---------------------------------------------------------------------------
__global__ void cvt_x_kernel(const float* __restrict__ src) {
    size_t i = (size_t)blockIdx.x * 256 + threadIdx.x;   // float4 units
    float4 v = reinterpret_cast<const float4*>(src)[i];
    reinterpret_cast<__nv_bfloat162*>(g_Ab)[i * 2 + 0] = __floats2bfloat162_rn(v.x, v.y);
    reinterpret_cast<__nv_bfloat162*>(g_Ab)[i * 2 + 1] = __floats2bfloat162_rn(v.z, v.w);
}

// ---------------------------------------------------------------------------
// Top-4 insert on embedded-score floats (descending)
// ---------------------------------------------------------------------------
__device__ __forceinline__ void top4_ins(float* b, float s) {
    if (s <= b[3]) return;
    int p = 3;
#pragma unroll
    for (int t = 0; t < 3; ++t) {
        if (p > 0 && s > b[p - 1]) { b[p] = b[p - 1]; --p; }
    }
    b[p] = s;
}

// ---------------------------------------------------------------------------
// Main kernel: bf16 HMMA, warp tile 64x32, fully warp-private B pipelines.
// k-loop addressing fully strength-reduced to precomputed constants.
// No bar.sync anywhere in the k-loop.
// ---------------------------------------------------------------------------
__global__ void __launch_bounds__(NTHR, 2)
vq_main_kernel() {
    extern __shared__ char smem[];
    uint32_t sb = smem_u32(smem);

    const int tid  = threadIdx.x;
    const int lane = tid & 31;
    const int w    = tid >> 5;     // warp 0..7: owns codes [w*32, w*32+32) per chunk
    const int q    = lane & 3;
    const int m0   = blockIdx.x * MT;

    // ---- Prologue: persistent A (cooperative; part of group G0) ----
#pragma unroll
    for (int j = 0; j < 16; ++j) {            // 4096 16B chunks
        int id = tid + j * 256;
        int row = id >> 6, c = id & 63;       // 64 chunks per 1024B row
        const void* src = g_Ab + (size_t)(m0 + row) * DIM + c * 8;
        uint32_t dst = sb + SM_A + row * 1024 + (c >> 3) * 128
                       + (((c & 7) ^ (row & 7)) * 16);
        cp_async16(dst, src);
    }

    // Per-thread B-fill constants. Thread covers rows row0+8j (j=0..3), chunk c0.
    const int row0 = lane >> 2;               // 0..7
    const int c0   = lane & 3;
    uint64_t gB;
    asm("cvta.to.global.u64 %0, %1;" : "=l"(gB) : "l"(g_Bb));
    const uint64_t pbase = gB
        + (uint32_t)(((w * 32 + row0) * 512 + c0 * 8) * 2);           // bytes
    const uint32_t d0 = (uint32_t)(w * W_SLICE + row0 * 64
                                   + ((c0 ^ ((row0 >> 1) & 3)) * 16));

    // ---- Precomputed ldmatrix address constants ----
    // A: addr = Ka[sub][par] + mf*16384 + offA, offA = (st>>1)*128.
    //    cA = 4*st + 2*sub + v, v = lane>>4; row&7 = (lane&15)&7 (mf-invariant).
    const int vA  = lane >> 4;
    const int r7  = (lane & 15) & 7;
    uint32_t Ka[2][2];
#pragma unroll
    for (int sub = 0; sub < 2; ++sub)
#pragma unroll
        for (int par = 0; par < 2; ++par) {
            int cb = 4 * par + 2 * sub + vA;        // cA & 7
            Ka[sub][par] = sb + SM_A + (uint32_t)((lane & 15) * 1024
                            + ((cb ^ r7) * 16));
        }
    // B: addr = bb + Bo[p][sub];  bb = stage base + w*W_SLICE.
    uint32_t Bo[2][2];
    {
        int mi   = lane >> 3;
        int noff = (mi >> 1) * 8;
        int kc   = mi & 1;
#pragma unroll
        for (int p = 0; p < 2; ++p)
#pragma unroll
            for (int sub = 0; sub < 2; ++sub) {
                int rloc = p * 16 + noff + (lane & 7);
                int c    = sub * 2 + kc;
                Bo[p][sub] = (uint32_t)(rloc * 64
                              + ((c ^ ((rloc >> 1) & 3)) * 16));
            }
    }
    const uint32_t bb0 = sb + SM_B + w * W_SLICE;   // stage-0 B base

    // Fill gs=0 (group G0, with A) and gs=1 (G1).
    {
        uint32_t fb = bb0 + 0 * B_STAGE + (d0 - w * W_SLICE);
        // NOTE: d0 already contains w*W_SLICE; recompute cleanly:
        fb = sb + SM_B + 0 * B_STAGE + d0;
#pragma unroll
        for (int j = 0; j < 4; ++j) cp_async16g(fb + j * 512, pbase + j * 8192);
        CP_COMMIT();
    }
    {
        uint32_t fb = sb + SM_B + 1 * B_STAGE + d0;
#pragma unroll
        for (int j = 0; j < 4; ++j) cp_async16g(fb + j * 512, pbase + 64 + j * 8192);
        CP_COMMIT();
    }

    asm volatile("cp.async.wait_group 1;" ::: "memory");   // G0: A + slice0
    __syncthreads();                                       // A visible to all

    // per-thread running top-2 (embedded-index floats) for 8 row-slots [mf][h]
    float tb1[4][2], tb2[4][2];
#pragma unroll
    for (int a = 0; a < 4; ++a)
#pragma unroll
        for (int b = 0; b < 2; ++b) { tb1[a][b] = -FLT_MAX; tb2[a][b] = -FLT_MAX; }

    // Cycling pipeline registers.
    uint32_t bb_cur  = sb + SM_B + 0 * B_STAGE + w * W_SLICE;   // stage gs%3
    uint32_t fb_cur  = sb + SM_B + 2 * B_STAGE + d0;            // stage (gs+2)%3
    const uint32_t bb_lo = sb + SM_B + w * W_SLICE;
    const uint32_t bb_hi = bb_lo + 2 * B_STAGE;
    const uint32_t fb_lo = sb + SM_B + d0;
    const uint32_t fb_hi = fb_lo + 2 * B_STAGE;

#pragma unroll 1
    for (int ch = 0; ch < NCHUNK; ++ch) {
        const int n0 = ch * BN;

        float acc[4][4][4];
#pragma unroll
        for (int a = 0; a < 4; ++a)
#pragma unroll
            for (int b = 0; b < 4; ++b)
#pragma unroll
                for (int c = 0; c < 4; ++c) acc[a][b][c] = 0.f;

        uint32_t offA = 0;                      // (st>>1)*128
#pragma unroll 1
        for (int stp = 0; stp < KSTEPS; stp += 2) {
#pragma unroll
            for (int par = 0; par < 2; ++par) {   // st = stp + par (par static)
                const int st = stp + par;
                const int gs = ch * KSTEPS + st;

                // ---- A fragments, sub 0 (constants + 1 add each) ----
                uint32_t afr[4][4];
#pragma unroll
                for (int mf = 0; mf < 4; ++mf)
                    ldmatrix_x4(afr[mf][0], afr[mf][1], afr[mf][2], afr[mf][3],
                                Ka[0][par] + (uint32_t)(mf * 16384) + offA);

                // Refill stage (gs+2)%3 BEFORE the wait.
                if (gs + 2 < NSTEPS) {
                    const int g2 = gs + 2;
                    uint64_t src = pbase
                        + (uint32_t)(((g2 >> 4) << 18) + ((g2 & 15) << 6));
#pragma unroll
                    for (int j = 0; j < 4; ++j)
                        cp_async16g(fb_cur + j * 512, src + j * 8192);
                    CP_COMMIT();
                } else {
                    CP_COMMIT();           // keep group arithmetic uniform
                }
                fb_cur = (fb_cur >= fb_hi) ? fb_lo : (fb_cur + B_STAGE);

                // Own fill of stage gs%3 complete (newest stays in flight).
                asm volatile("cp.async.wait_group 1;" ::: "memory");

#pragma unroll
                for (int sub = 0; sub < 2; ++sub) {    // 2 x k16 per BK=32
                    if (sub == 1) {
#pragma unroll
                        for (int mf = 0; mf < 4; ++mf)
                            ldmatrix_x4(afr[mf][0], afr[mf][1],
                                        afr[mf][2], afr[mf][3],
                                        Ka[1][par] + (uint32_t)(mf * 16384) + offA);
                    }
                    // ---- B fragments: constants + 1 add each ----
                    uint32_t bfr[4][2];
#pragma unroll
                    for (int p = 0; p < 2; ++p)
                        ldmatrix_x4(bfr[p*2][0], bfr[p*2][1],
                                    bfr[p*2+1][0], bfr[p*2+1][1],
                                    bb_cur + Bo[p][sub]);
#pragma unroll
                    for (int mf = 0; mf < 4; ++mf)
#pragma unroll
                        for (int nf = 0; nf < 4; ++nf)
                            mma_bf16(acc[mf][nf][0], acc[mf][nf][1],
                                     acc[mf][nf][2], acc[mf][nf][3],
                                     afr[mf][0], afr[mf][1],
                                     afr[mf][2], afr[mf][3],
                                     bfr[nf][0], bfr[nf][1]);
                }
                bb_cur = (bb_cur >= bb_hi) ? bb_lo : (bb_cur + B_STAGE);
            }
            offA += 128;
        }

        // ---- epilogue: branchless embedded-index top-2 (no barriers) ----
        float e2h[8];
#pragma unroll
        for (int nf = 0; nf < 4; ++nf) {
            float2 p = *reinterpret_cast<const float2*>(
                &g_e2[n0 + w * 32 + nf * 8 + q * 2]);
            e2h[nf * 2] = 0.5f * p.x; e2h[nf * 2 + 1] = 0.5f * p.y;
        }
#pragma unroll
        for (int mf = 0; mf < 4; ++mf)
#pragma unroll
            for (int h = 0; h < 2; ++h)
#pragma unroll
                for (int nf = 0; nf < 4; ++nf) {
                    uint32_t cloc = (uint32_t)(n0 + w * 32 + nf * 8 + q * 2);
                    float s0 = embed_idx(acc[mf][nf][h*2+0] - e2h[nf*2+0], cloc);
                    float s1 = embed_idx(acc[mf][nf][h*2+1] - e2h[nf*2+1], cloc + 1);
                    top2f(tb1[mf][h], tb2[mf][h], s0);
                    top2f(tb1[mf][h], tb2[mf][h], s1);
                }
    }

    // ---- final merge: 32 contributors x top-2 per row -> top-4 ----
    asm volatile("cp.async.wait_group 0;" ::: "memory");   // drain tail groups
    __syncthreads();                       // B stages dead; alias merge buffer
    float2* mbuf = reinterpret_cast<float2*>(smem + SM_B); // [64 rows][32]
#pragma unroll
    for (int mf = 0; mf < 4; ++mf)
#pragma unroll
        for (int h = 0; h < 2; ++h) {
            int row = mf * 16 + h * 8 + (lane >> 2);
            mbuf[row * 32 + w * 4 + q] = make_float2(tb1[mf][h], tb2[mf][h]);
        }
    __syncthreads();
    if (tid < MT) {
        float bs[4];
#pragma unroll
        for (int e = 0; e < 4; ++e) bs[e] = -FLT_MAX;
        for (int e = 0; e < 32; ++e) {
            float2 v = mbuf[tid * 32 + e];
            top4_ins(bs, v.x);
            top4_ins(bs, v.y);
        }
        g_top4[m0 + tid] = make_int4(
            (int)(__float_as_uint(bs[0]) & IDXMASK),
            (int)(__float_as_uint(bs[1]) & IDXMASK),
            (int)(__float_as_uint(bs[2]) & IDXMASK),
            (int)(__float_as_uint(bs[3]) & IDXMASK));
    }
}

// ---------------------------------------------------------------------------
// Refine + gather, warp-per-row: exact fp32 re-score of top-4, copy winner.
// ---------------------------------------------------------------------------
__global__ void refine_gather_kernel(const float* __restrict__ x,
                                     const float* __restrict__ emb,
                                     float* __restrict__ out) {
    int row  = (blockIdx.x * blockDim.x + threadIdx.x) >> 5;
    int lane = threadIdx.x & 31;
    int4 cnd = g_top4[row];
    int cand[4] = {cnd.x, cnd.y, cnd.z, cnd.w};

    const float4* xr = reinterpret_cast<const float4*>(x + (size_t)row * DIM);
    float d[4] = {0.f, 0.f, 0.f, 0.f};
#pragma unroll
    for (int j = 0; j < 4; ++j) {
        float4 xv = xr[lane + j * 32];
#pragma unroll
        for (int c = 0; c < 4; ++c) {
            const float4* er = reinterpret_cast<const float4*>(
                emb + (size_t)cand[c] * DIM);
            float4 e = er[lane + j * 32];
            d[c] += xv.x * e.x + xv.y * e.y + xv.z * e.z + xv.w * e.w;
        }
    }
#pragma unroll
    for (int o = 16; o; o >>= 1)
#pragma unroll
        for (int c = 0; c < 4; ++c)
            d[c] += __shfl_xor_sync(0xffffffffu, d[c], o);

    float bs = d[0] - 0.5f * g_e2[cand[0]];
    int   bi = cand[0];
#pragma unroll
    for (int c = 1; c < 4; ++c) {
        float s = d[c] - 0.5f * g_e2[cand[c]];
        if (s > bs || (s == bs && cand[c] < bi)) { bs = s; bi = cand[c]; }
    }

    const float4* src = reinterpret_cast<const float4*>(emb + (size_t)bi * DIM);
    float4*       dst = reinterpret_cast<float4*>(out + (size_t)row * DIM);
#pragma unroll
    for (int j = 0; j < 4; ++j) dst[lane + j * 32] = src[lane + j * 32];
}

// ---------------------------------------------------------------------------
extern "C" void kernel_launch(void* const* d_in, const int* in_sizes, int n_in,
                              void* d_out, int out_size) {
    const float* x   = (const float*)d_in[0];
    const float* emb = (const float*)d_in[1];
    float*       out = (float*)d_out;

    cudaFuncSetAttribute(vq_main_kernel,
                         cudaFuncAttributeMaxDynamicSharedMemorySize, SMEM_TOTAL);

    cvt_e2_kernel<<<K_CODES / 8, 256>>>(emb);
    cvt_x_kernel<<<(M_TOTAL * DIM / 4) / 256, 256>>>(x);
    vq_main_kernel<<<M_TOTAL / MT, NTHR, SMEM_TOTAL>>>();
    refine_gather_kernel<<<M_TOTAL / 8, 256>>>(x, emb, out);
}